// round 16
// baseline (speedup 1.0000x reference)
#include <cuda_runtime.h>
#include <cuda_fp16.h>
#include <math.h>
#include <stdint.h>

#define Bc     8
#define Nc     1000
#define Dc     64
#define ADc    32
#define NEc    4000      // E * N
#define ACOLS  8000      // 2 * E * N
#define KCH    32        // K per chunk
#define NCHUNK 125       // 4000 / 32
#define ASTR   40        // fp16 A smem stride (halves)
#define BSTR   72        // B smem stride (halves)
#define CHW    32000     // halves per chunk slab in tiled A' (1000*32)

// k_gru smem geometry (bytes)
#define XSTR   200       // X stride (halves)
#define WSTR   72        // W stride (halves)
#define RSTR   72        // rs stride (halves)
#define SSTR   68        // state stride (floats)
#define XH_B   (64 * XSTR * 2)            // 25600
#define W_B    (192 * WSTR * 2)           // 27648
#define RS_B   (64 * RSTR * 2)            // 9216
#define ST_B   (64 * SSTR * 4)            // 17408
#define GRU_SMEM (XH_B + W_B + RS_B + ST_B)   // 79872

// Scratch (static device globals; no allocation)
// g_Ah: chunk-tiled fp16 A': [b][half][ch][n][32]  (128 MB)
__device__ __half g_Ah[(size_t)Bc * 2 * NCHUNK * CHW];
__device__ __half g_sh[2][Bc][NEc][Dc];            // S (fp16), k-major rows
__device__ __half g_ah2[2][Bc][Nc][Dc];            // a_in / a_out (fp16)
__device__ float  g_state[2][Bc][Nc][Dc];          // s1 / s2 (fp32)
__device__ __half g_WTh[192][192];                 // [k][out]: r|z|h fp16 (h k>=128 zeroed)
__device__ __half g_Wh2Th[Dc][Dc];                 // [k][f] = W_h[f][128+k] fp16

// ---------------------------------------------------------------------------
// helpers
// ---------------------------------------------------------------------------
__device__ __forceinline__ void cp_async16(uint32_t dst, const void* src) {
    asm volatile("cp.async.cg.shared.global [%0], [%1], 16;\n" :: "r"(dst), "l"(src));
}
__device__ __forceinline__ void cp_commit() {
    asm volatile("cp.async.commit_group;\n");
}
__device__ __forceinline__ void ldm4(uint32_t* r, uint32_t addr) {
    asm volatile("ldmatrix.sync.aligned.m8n8.x4.shared.b16 {%0,%1,%2,%3}, [%4];"
                 : "=r"(r[0]), "=r"(r[1]), "=r"(r[2]), "=r"(r[3]) : "r"(addr));
}
__device__ __forceinline__ void ldm4t(uint32_t* r, uint32_t addr) {
    asm volatile("ldmatrix.sync.aligned.m8n8.x4.trans.shared.b16 {%0,%1,%2,%3}, [%4];"
                 : "=r"(r[0]), "=r"(r[1]), "=r"(r[2]), "=r"(r[3]) : "r"(addr));
}
__device__ __forceinline__ void mma_f16(float* c, const uint32_t* a,
                                        uint32_t b0, uint32_t b1) {
    asm volatile("mma.sync.aligned.m16n8k16.row.col.f32.f16.f16.f32 "
                 "{%0,%1,%2,%3},{%4,%5,%6,%7},{%8,%9},{%0,%1,%2,%3};"
                 : "+f"(c[0]), "+f"(c[1]), "+f"(c[2]), "+f"(c[3])
                 : "r"(a[0]), "r"(a[1]), "r"(a[2]), "r"(a[3]), "r"(b0), "r"(b1));
}

// ---------------------------------------------------------------------------
// A fp32 -> fp16, chunk-tiled: A'[b][half][ch][n][32].
// ---------------------------------------------------------------------------
__global__ void __launch_bounds__(256) k_convA(const float* __restrict__ A) {
    size_t idx = (size_t)blockIdx.x * 256 + threadIdx.x;   // float4 index
    float4 v = ((const float4*)A)[idx];
    __half2 h0 = __floats2half2_rn(v.x, v.y);
    __half2 h1 = __floats2half2_rn(v.z, v.w);
    uint2 pk = make_uint2(*(uint32_t*)&h0, *(uint32_t*)&h1);

    size_t bn = idx / 2000;
    int c4 = (int)(idx % 2000);
    int b = (int)(bn / 1000), n = (int)(bn % 1000);
    int c = c4 * 4;
    int half = (c >= NEc) ? 1 : 0;
    int cc = c - half * NEc;
    int ch = cc >> 5, off = cc & 31;
    size_t dsth = (((size_t)b * 2 + half) * NCHUNK + ch) * CHW + (size_t)n * 32 + off;
    *(uint2*)&g_Ah[dsth] = pk;
}

// ---------------------------------------------------------------------------
// One-time weight prep (fp16)
// ---------------------------------------------------------------------------
__global__ void __launch_bounds__(256) k_prepW(const float* __restrict__ W_r,
                                               const float* __restrict__ W_z,
                                               const float* __restrict__ W_h) {
    int idx = blockIdx.x * 256 + threadIdx.x;
    if (idx < 192 * 192) {
        int k = idx / 192, out = idx % 192;
        int grp = out >> 6, f = out & 63;
        const float* W = (grp == 0) ? W_r : (grp == 1) ? W_z : W_h;
        float v = W[f * 192 + k];
        if (grp == 2 && k >= 128) v = 0.f;
        g_WTh[k][out] = __float2half_rn(v);
    }
    if (idx < 64 * 64) {
        int k = idx / 64, f = idx % 64;
        g_Wh2Th[k][f] = __float2half_rn(W_h[f * 192 + 128 + k]);
    }
}

// ---------------------------------------------------------------------------
// s projection (tiled GEMM) -> fp16 S, k-major rows. grid (125, 8), block 256.
// ---------------------------------------------------------------------------
__global__ void __launch_bounds__(256) k_compute_s2(
    const float* __restrict__ Xext, int use_ext,
    const float* __restrict__ W_in, const float* __restrict__ W_out) {
    const float* X = use_ext ? Xext : &g_state[0][0][0][0];
    int rb = blockIdx.x, cb = blockIdx.y;
    __shared__ float x_sm[64][64];
    __shared__ float wT[64][64];
    int t = threadIdx.x;

#pragma unroll
    for (int i = 0; i < 4; i++) {
        int idx = i * 256 + t;
        int r = idx >> 4, c4 = idx & 15;
        int gr = rb * 64 + r;
        *(float4*)&x_sm[r][c4 * 4] = *(const float4*)&X[(size_t)gr * 64 + c4 * 4];
    }
    const float* Wsrc = (cb < 4) ? (W_in + (size_t)cb * 64 * 64)
                                 : (W_out + (size_t)(cb - 4) * 64 * 64);
#pragma unroll
    for (int i = 0; i < 4; i++) {
        int idx = i * 256 + t;
        int cl = idx >> 4, k4 = idx & 15;
        float4 v = *(const float4*)&Wsrc[cl * 64 + k4 * 4];
        wT[k4 * 4 + 0][cl] = v.x;
        wT[k4 * 4 + 1][cl] = v.y;
        wT[k4 * 4 + 2][cl] = v.z;
        wT[k4 * 4 + 3][cl] = v.w;
    }
    __syncthreads();

    int ty = t >> 5, tx = t & 31;
    float acc[8][2];
#pragma unroll
    for (int i = 0; i < 8; i++) { acc[i][0] = 0.f; acc[i][1] = 0.f; }

#pragma unroll
    for (int k4 = 0; k4 < 16; k4++) {
        float4 xv[8];
#pragma unroll
        for (int i = 0; i < 8; i++) xv[i] = *(float4*)&x_sm[ty * 8 + i][k4 * 4];
#pragma unroll
        for (int q = 0; q < 4; q++) {
            float2 wv = *(float2*)&wT[k4 * 4 + q][tx * 2];
#pragma unroll
            for (int i = 0; i < 8; i++) {
                float xs = (q == 0) ? xv[i].x : (q == 1) ? xv[i].y
                         : (q == 2) ? xv[i].z : xv[i].w;
                acc[i][0] += xs * wv.x;
                acc[i][1] += xs * wv.y;
            }
        }
    }

    int cbase = cb * 64 + tx * 2;
    int half = cbase >> 8, e = (cbase >> 6) & 3, f = cbase & 63;
#pragma unroll
    for (int i = 0; i < 8; i++) {
        int gr = rb * 64 + ty * 8 + i;
        int b = gr / 1000, n = gr % 1000;
        __half2 hv = __floats2half2_rn(acc[i][0], acc[i][1]);
        *(__half2*)&g_sh[half][b][e * 1000 + n][f] = hv;
    }
}

// ---------------------------------------------------------------------------
// Big adjacency GEMM, M=32 tiles for occupancy: grid (32, 2, 8) = 1024 CTAs,
// 128 threads (2m x 2n warps; warp tile 16x32). 4-stage cp.async, 28.7 KB smem.
// ---------------------------------------------------------------------------
__global__ void __launch_bounds__(128) k_biggemm_f16(int dummy) {
    __shared__ __half Asm[4][32 * ASTR];   // 4 x 2560 B
    __shared__ __half Bsm[4][32 * BSTR];   // 4 x 4608 B

    int rb = blockIdx.x, half = blockIdx.y, b = blockIdx.z;
    int row0 = rb * 32;
    const __half* Abh = g_Ah + ((size_t)b * 2 + half) * NCHUNK * CHW;
    const __half* Sbh = &g_sh[half][b][0][0];

    int t = threadIdx.x, lane = t & 31, warp = t >> 5;
    int wm = warp & 1, wn = warp >> 1;

    // A cp.async: 32 rows x 4 segs of 16B -> 1 op/thread
    const __half* asrc; uint32_t adst;
    {
        int row = t >> 2, seg = t & 3;
        int gr = row0 + row; if (gr > Nc - 1) gr = Nc - 1;
        asrc = Abh + (size_t)gr * 32 + seg * 8;
        adst = (uint32_t)(row * ASTR + seg * 8) * 2u;
    }
    // B cp.async: 32 rows x 8 segs of 16B -> 2 ops/thread
    const __half* bsrc[2]; uint32_t bdst[2];
#pragma unroll
    for (int j = 0; j < 2; j++) {
        int flat = j * 128 + t;
        int row = flat >> 3, seg = flat & 7;
        bsrc[j] = Sbh + (size_t)row * Dc + seg * 8;
        bdst[j] = (uint32_t)(row * BSTR + seg * 8) * 2u;
    }

    uint32_t a_base[4], b_base[4];
#pragma unroll
    for (int s = 0; s < 4; s++) {
        a_base[s] = (uint32_t)__cvta_generic_to_shared(&Asm[s][0]);
        b_base[s] = (uint32_t)__cvta_generic_to_shared(&Bsm[s][0]);
    }

    uint32_t a_off[2];
#pragma unroll
    for (int kk = 0; kk < 2; kk++) {
        int row = wm * 16 + ((lane >> 3) & 1) * 8 + (lane & 7);
        int col = kk * 16 + (lane >> 4) * 8;
        a_off[kk] = (uint32_t)(row * ASTR + col) * 2u;
    }
    uint32_t b_off[2][2];   // [g][kk]
#pragma unroll
    for (int g = 0; g < 2; g++)
#pragma unroll
        for (int kk = 0; kk < 2; kk++) {
            int krow = kk * 16 + (lane & 15);
            int ncol = wn * 32 + g * 16 + (lane >> 4) * 8;
            b_off[g][kk] = (uint32_t)(krow * BSTR + ncol) * 2u;
        }

    float acc[4][4];
#pragma unroll
    for (int nt = 0; nt < 4; nt++)
#pragma unroll
        for (int c = 0; c < 4; c++) acc[nt][c] = 0.f;

#pragma unroll
    for (int ch = 0; ch < 3; ch++) {
        cp_async16(a_base[ch] + adst, asrc + (size_t)ch * CHW);
#pragma unroll
        for (int j = 0; j < 2; j++)
            cp_async16(b_base[ch] + bdst[j], bsrc[j] + (size_t)ch * KCH * Dc);
        cp_commit();
    }

    for (int i = 0; i < NCHUNK; i++) {
        asm volatile("cp.async.wait_group 2;\n");
        __syncthreads();

        if (i + 3 < NCHUNK) {
            int s = (i + 3) & 3;
            cp_async16(a_base[s] + adst, asrc + (size_t)(i + 3) * CHW);
#pragma unroll
            for (int j = 0; j < 2; j++)
                cp_async16(b_base[s] + bdst[j], bsrc[j] + (size_t)(i + 3) * KCH * Dc);
        }
        cp_commit();

        uint32_t ab = a_base[i & 3], bb = b_base[i & 3];
        uint32_t aF[2][4];
        uint32_t bF[2][2][4];
#pragma unroll
        for (int kk = 0; kk < 2; kk++) ldm4(aF[kk], ab + a_off[kk]);
#pragma unroll
        for (int kk = 0; kk < 2; kk++)
#pragma unroll
            for (int g = 0; g < 2; g++) ldm4t(bF[kk][g], bb + b_off[g][kk]);

#pragma unroll
        for (int kk = 0; kk < 2; kk++)
#pragma unroll
            for (int nt = 0; nt < 4; nt++) {
                int g = nt >> 1, sel = nt & 1;
                mma_f16(acc[nt], aF[kk],
                        bF[kk][g][sel * 2], bF[kk][g][sel * 2 + 1]);
            }
    }

    __half (*C)[Dc] = g_ah2[half][b];
    int r_a = row0 + wm * 16 + (lane >> 2);
    int r_b = r_a + 8;
#pragma unroll
    for (int nt = 0; nt < 4; nt++) {
        int col = wn * 32 + nt * 8 + (lane & 3) * 2;
        if (r_a < Nc) *(__half2*)&C[r_a][col] = __floats2half2_rn(acc[nt][0], acc[nt][1]);
        if (r_b < Nc) *(__half2*)&C[r_b][col] = __floats2half2_rn(acc[nt][2], acc[nt][3]);
    }
}

// ---------------------------------------------------------------------------
// Fused tensor-core GRU (unchanged from R14 winner).
// ---------------------------------------------------------------------------
__global__ void __launch_bounds__(128) k_gru(const float* __restrict__ ext_state,
                                             int use_ext, int out_idx) {
    extern __shared__ char gsm[];
    __half* Xh  = (__half*)gsm;                    // [64][200]
    __half* Wsm = (__half*)(gsm + XH_B);           // [192][72]
    __half* RSs = (__half*)(gsm + XH_B + W_B);     // [64][72]
    float*  STs = (float*)(gsm + XH_B + W_B + RS_B); // [64][68]

    int rb = blockIdx.x;
    int row0 = rb * 64;
    int t = threadIdx.x, lane = t & 31, warp = t >> 5;

    uint32_t xh_u  = (uint32_t)__cvta_generic_to_shared(Xh);
    uint32_t wsm_u = (uint32_t)__cvta_generic_to_shared(Wsm);
    uint32_t rs_u  = (uint32_t)__cvta_generic_to_shared(RSs);

#pragma unroll
    for (int j = 0; j < 8; j++) {
        int flat = j * 128 + t;
        int row = flat >> 4, seg = flat & 15;
        int gr = row0 + row;
        int b = gr / 1000, n = gr % 1000;
        const __half* p = (seg < 8) ? &g_ah2[0][b][n][seg * 8]
                                    : &g_ah2[1][b][n][(seg - 8) * 8];
        cp_async16(xh_u + (uint32_t)(row * XSTR + seg * 8) * 2u, p);
    }
#pragma unroll
    for (int j = 0; j < 12; j++) {
        int flat = j * 128 + t;
        int k = flat >> 3, seg = flat & 7;
        cp_async16(wsm_u + (uint32_t)(k * WSTR + seg * 8) * 2u, &g_WTh[k][seg * 8]);
    }
    cp_commit();
#pragma unroll
    for (int j = 0; j < 8; j++) {
        int flat = j * 128 + t;
        int row = flat >> 4, c4 = flat & 15;
        int gr = row0 + row;
        int b = gr / 1000, n = gr % 1000;
        const float* sp = use_ext ? (ext_state + (size_t)gr * 64)
                                  : &g_state[0][b][n][0];
        float4 v = *(const float4*)&sp[c4 * 4];
        *(float4*)&STs[row * SSTR + c4 * 4] = v;
        __half2 h0 = __floats2half2_rn(v.x, v.y);
        __half2 h1 = __floats2half2_rn(v.z, v.w);
        *(uint2*)&Xh[row * XSTR + 128 + c4 * 4] = make_uint2(*(uint32_t*)&h0, *(uint32_t*)&h1);
    }

    int a_row = warp * 16 + ((lane >> 3) & 1) * 8 + (lane & 7);
    int acol8 = (lane >> 4) * 8;
    uint32_t base_a  = xh_u + (uint32_t)(a_row * XSTR + acol8) * 2u;
    uint32_t base_rs = rs_u + (uint32_t)(a_row * RSTR + acol8) * 2u;
    int b_k = lane & 15, bcol = (lane >> 4) * 8;

    float acc[3][8][4];
#pragma unroll
    for (int cb = 0; cb < 3; cb++)
#pragma unroll
        for (int nt = 0; nt < 8; nt++)
#pragma unroll
            for (int c = 0; c < 4; c++) acc[cb][nt][c] = 0.f;

    for (int cb = 0; cb < 3; cb++) {
        asm volatile("cp.async.wait_group 0;\n");
        __syncthreads();

#pragma unroll
        for (int kc = 0; kc < 6; kc++) {
#pragma unroll
            for (int kk = 0; kk < 2; kk++) {
                int kb = kc * 32 + kk * 16;
                uint32_t aF[4];
                ldm4(aF, base_a + (uint32_t)kb * 2u);
                uint32_t bF[4][4];
#pragma unroll
                for (int g = 0; g < 4; g++)
                    ldm4t(bF[g], wsm_u + (uint32_t)((kb + b_k) * WSTR + g * 16 + bcol) * 2u);
#pragma unroll
                for (int nt = 0; nt < 8; nt++) {
                    int g = nt >> 1, sel = nt & 1;
                    mma_f16(acc[cb][nt], aF, bF[g][sel * 2], bF[g][sel * 2 + 1]);
                }
            }
        }
        __syncthreads();

        if (cb < 2) {
#pragma unroll
            for (int j = 0; j < 12; j++) {
                int flat = j * 128 + t;
                int k = flat >> 3, seg = flat & 7;
                cp_async16(wsm_u + (uint32_t)(k * WSTR + seg * 8) * 2u,
                           &g_WTh[k][(cb + 1) * 64 + seg * 8]);
            }
        } else {
#pragma unroll
            for (int j = 0; j < 4; j++) {
                int flat = j * 128 + t;
                int k = flat >> 3, seg = flat & 7;
                cp_async16(wsm_u + (uint32_t)(k * WSTR + seg * 8) * 2u,
                           &g_Wh2Th[k][seg * 8]);
            }
        }
        cp_commit();
    }

    int lr_a = warp * 16 + (lane >> 2);
    int lr_b = lr_a + 8;
#pragma unroll
    for (int nt = 0; nt < 8; nt++) {
        int c = nt * 8 + (lane & 3) * 2;
        float2 sa = *(float2*)&STs[lr_a * SSTR + c];
        float2 sb = *(float2*)&STs[lr_b * SSTR + c];
        float ra0 = sa.x / (1.f + expf(-acc[0][nt][0]));
        float ra1 = sa.y / (1.f + expf(-acc[0][nt][1]));
        float rb0 = sb.x / (1.f + expf(-acc[0][nt][2]));
        float rb1 = sb.y / (1.f + expf(-acc[0][nt][3]));
        *(__half2*)&RSs[lr_a * RSTR + c] = __floats2half2_rn(ra0, ra1);
        *(__half2*)&RSs[lr_b * RSTR + c] = __floats2half2_rn(rb0, rb1);
    }
    asm volatile("cp.async.wait_group 0;\n");
    __syncthreads();

#pragma unroll
    for (int nt = 0; nt < 8; nt++)
#pragma unroll
        for (int c = 0; c < 4; c++) acc[0][nt][c] = 0.f;

#pragma unroll
    for (int kc = 0; kc < 2; kc++) {
#pragma unroll
        for (int kk = 0; kk < 2; kk++) {
            int kb = kc * 32 + kk * 16;
            uint32_t aF[4];
            ldm4(aF, base_rs + (uint32_t)kb * 2u);
            uint32_t bF[4][4];
#pragma unroll
            for (int g = 0; g < 4; g++)
                ldm4t(bF[g], wsm_u + (uint32_t)((kb + b_k) * WSTR + g * 16 + bcol) * 2u);
#pragma unroll
            for (int nt = 0; nt < 8; nt++) {
                int g = nt >> 1, sel = nt & 1;
                mma_f16(acc[0][nt], aF, bF[g][sel * 2], bF[g][sel * 2 + 1]);
            }
        }
    }

#pragma unroll
    for (int nt = 0; nt < 8; nt++) {
        int c = nt * 8 + (lane & 3) * 2;
        float2 sa = *(float2*)&STs[lr_a * SSTR + c];
        float2 sb = *(float2*)&STs[lr_b * SSTR + c];
        float za0 = 1.f / (1.f + expf(-acc[1][nt][0]));
        float za1 = 1.f / (1.f + expf(-acc[1][nt][1]));
        float zb0 = 1.f / (1.f + expf(-acc[1][nt][2]));
        float zb1 = 1.f / (1.f + expf(-acc[1][nt][3]));
        float ha0 = tanhf(acc[2][nt][0] + acc[0][nt][0]);
        float ha1 = tanhf(acc[2][nt][1] + acc[0][nt][1]);
        float hb0 = tanhf(acc[2][nt][2] + acc[0][nt][2]);
        float hb1 = tanhf(acc[2][nt][3] + acc[0][nt][3]);
        int gra = row0 + lr_a, grb = row0 + lr_b;
        int ba = gra / 1000, na = gra % 1000;
        int bb2 = grb / 1000, nb = grb % 1000;
        *(float2*)&g_state[out_idx][ba][na][c] =
            make_float2((1.f - za0) * sa.x + za0 * ha0,
                        (1.f - za1) * sa.y + za1 * ha1);
        *(float2*)&g_state[out_idx][bb2][nb][c] =
            make_float2((1.f - zb0) * sb.x + zb0 * hb0,
                        (1.f - zb1) * sb.y + zb1 * hb1);
    }
}

// ---------------------------------------------------------------------------
// out[b,n] = sum_f tanh( sum_{j<96} [s2|annot][j] * Wo1[f,j] ) * Wo2[f]
// ---------------------------------------------------------------------------
__global__ void k_final(const float* __restrict__ annotation,
                        const float* __restrict__ Wo1,
                        const float* __restrict__ Wo2,
                        float* __restrict__ out) {
    __shared__ float join[4][96];
    __shared__ float terms[4][64];
    int t = threadIdx.x;
    int base = blockIdx.x * 4;

    for (int idx = t; idx < 4 * 96; idx += 256) {
        int lr = idx / 96, j = idx % 96;
        int bn = base + lr;
        int b = bn / Nc, n = bn % Nc;
        join[lr][j] = (j < Dc) ? g_state[1][b][n][j]
                               : annotation[(size_t)bn * ADc + (j - Dc)];
    }
    __syncthreads();

    int f = t & 63, q = t >> 6;
    const float4* w = (const float4*)(Wo1 + (size_t)f * 96);
    float acc = 0.f;
#pragma unroll
    for (int j4 = 0; j4 < 24; j4++) {
        float4 wv = w[j4];
        float4 jv = *(float4*)&join[q][j4 * 4];
        acc += wv.x * jv.x + wv.y * jv.y + wv.z * jv.z + wv.w * jv.w;
    }
    terms[q][f] = tanhf(acc) * Wo2[f];
    __syncthreads();

    if (f == 0) {
        float s = 0.f;
#pragma unroll
        for (int i = 0; i < Dc; i++) s += terms[q][i];
        out[base + q] = s;
    }
}

// ---------------------------------------------------------------------------
extern "C" void kernel_launch(void* const* d_in, const int* in_sizes, int n_in,
                              void* d_out, int out_size) {
    const float* prop_state = (const float*)d_in[0];
    const float* annotation = (const float*)d_in[1];
    const float* A          = (const float*)d_in[2];
    const float* W_in       = (const float*)d_in[3];
    const float* W_out      = (const float*)d_in[4];
    const float* W_r        = (const float*)d_in[5];
    const float* W_z        = (const float*)d_in[6];
    const float* W_h        = (const float*)d_in[7];
    const float* Wo1        = (const float*)d_in[8];
    const float* Wo2        = (const float*)d_in[9];
    float* out = (float*)d_out;

    static int smem_set = 0;
    if (!smem_set) {
        cudaFuncSetAttribute(k_gru,
                             cudaFuncAttributeMaxDynamicSharedMemorySize, GRU_SMEM);
        smem_set = 1;
    }

    dim3 s_grid(125, 8);
    dim3 gemm_grid(32, 2, Bc);

    k_convA<<<Bc * Nc * ACOLS / 4 / 256, 256>>>(A);
    k_prepW<<<144, 256>>>(W_r, W_z, W_h);

    // ---- propagate step 1 (state = prop_state) ----
    k_compute_s2<<<s_grid, 256>>>(prop_state, 1, W_in, W_out);
    k_biggemm_f16<<<gemm_grid, 128>>>(0);
    k_gru<<<125, 128, GRU_SMEM>>>(prop_state, 1, 0);

    // ---- propagate step 2 (state = g_state[0]) ----
    k_compute_s2<<<s_grid, 256>>>(nullptr, 0, W_in, W_out);
    k_biggemm_f16<<<gemm_grid, 128>>>(0);
    k_gru<<<125, 128, GRU_SMEM>>>(nullptr, 0, 1);

    // ---- output head ----
    k_final<<<Bc * Nc / 4, 256>>>(annotation, Wo1, Wo2, out);
}

// round 17
// speedup vs baseline: 1.0391x; 1.0391x over previous
#include <cuda_runtime.h>
#include <cuda_fp16.h>
#include <math.h>
#include <stdint.h>

#define Bc     8
#define Nc     1000
#define Dc     64
#define ADc    32
#define NEc    4000      // E * N
#define ACOLS  8000      // 2 * E * N
#define KCH    32        // K per chunk
#define NCHUNK 125       // 4000 / 32
#define ASTR   40        // fp16 A smem stride (halves)
#define BSTR   72        // B smem stride (halves)
#define CHW    32000     // halves per chunk slab in tiled A' (1000*32)

// k_gru smem geometry (bytes)
#define XSTR   200       // X stride (halves)
#define WSTR   72        // W stride (halves)
#define RSTR   72        // rs stride (halves)
#define SSTR   68        // state stride (floats)
#define XH_B   (64 * XSTR * 2)            // 25600
#define W_B    (192 * WSTR * 2)           // 27648
#define RS_B   (64 * RSTR * 2)            // 9216
#define ST_B   (64 * SSTR * 4)            // 17408
#define GRU_SMEM (XH_B + W_B + RS_B + ST_B)   // 79872

// Scratch (static device globals; no allocation)
// g_Ah: chunk-tiled fp16 A': [b][half][ch][n][32]  (128 MB)
__device__ __half g_Ah[(size_t)Bc * 2 * NCHUNK * CHW];
__device__ __half g_sh[2][Bc][NEc][Dc];            // S (fp16), k-major rows
__device__ __half g_ah2[2][Bc][Nc][Dc];            // a_in / a_out (fp16)
__device__ float  g_state[2][Bc][Nc][Dc];          // s1 / s2 (fp32)
__device__ __half g_WTh[192][192];                 // [k][out]: r|z|h fp16 (h k>=128 zeroed)
__device__ __half g_Wh2Th[Dc][Dc];                 // [k][f] = W_h[f][128+k] fp16

// ---------------------------------------------------------------------------
// helpers
// ---------------------------------------------------------------------------
__device__ __forceinline__ void cp_async16(uint32_t dst, const void* src) {
    asm volatile("cp.async.cg.shared.global [%0], [%1], 16;\n" :: "r"(dst), "l"(src));
}
__device__ __forceinline__ void cp_commit() {
    asm volatile("cp.async.commit_group;\n");
}
__device__ __forceinline__ void ldm4(uint32_t* r, uint32_t addr) {
    asm volatile("ldmatrix.sync.aligned.m8n8.x4.shared.b16 {%0,%1,%2,%3}, [%4];"
                 : "=r"(r[0]), "=r"(r[1]), "=r"(r[2]), "=r"(r[3]) : "r"(addr));
}
__device__ __forceinline__ void ldm4t(uint32_t* r, uint32_t addr) {
    asm volatile("ldmatrix.sync.aligned.m8n8.x4.trans.shared.b16 {%0,%1,%2,%3}, [%4];"
                 : "=r"(r[0]), "=r"(r[1]), "=r"(r[2]), "=r"(r[3]) : "r"(addr));
}
__device__ __forceinline__ void mma_f16(float* c, const uint32_t* a,
                                        uint32_t b0, uint32_t b1) {
    asm volatile("mma.sync.aligned.m16n8k16.row.col.f32.f16.f16.f32 "
                 "{%0,%1,%2,%3},{%4,%5,%6,%7},{%8,%9},{%0,%1,%2,%3};"
                 : "+f"(c[0]), "+f"(c[1]), "+f"(c[2]), "+f"(c[3])
                 : "r"(a[0]), "r"(a[1]), "r"(a[2]), "r"(a[3]), "r"(b0), "r"(b1));
}

// ---------------------------------------------------------------------------
// A fp32 -> fp16, chunk-tiled: A'[b][half][ch][n][32].
// ---------------------------------------------------------------------------
__global__ void __launch_bounds__(256) k_convA(const float* __restrict__ A) {
    size_t idx = (size_t)blockIdx.x * 256 + threadIdx.x;   // float4 index
    float4 v = ((const float4*)A)[idx];
    __half2 h0 = __floats2half2_rn(v.x, v.y);
    __half2 h1 = __floats2half2_rn(v.z, v.w);
    uint2 pk = make_uint2(*(uint32_t*)&h0, *(uint32_t*)&h1);

    size_t bn = idx / 2000;
    int c4 = (int)(idx % 2000);
    int b = (int)(bn / 1000), n = (int)(bn % 1000);
    int c = c4 * 4;
    int half = (c >= NEc) ? 1 : 0;
    int cc = c - half * NEc;
    int ch = cc >> 5, off = cc & 31;
    size_t dsth = (((size_t)b * 2 + half) * NCHUNK + ch) * CHW + (size_t)n * 32 + off;
    *(uint2*)&g_Ah[dsth] = pk;
}

// ---------------------------------------------------------------------------
// One-time weight prep (fp16)
// ---------------------------------------------------------------------------
__global__ void __launch_bounds__(256) k_prepW(const float* __restrict__ W_r,
                                               const float* __restrict__ W_z,
                                               const float* __restrict__ W_h) {
    int idx = blockIdx.x * 256 + threadIdx.x;
    if (idx < 192 * 192) {
        int k = idx / 192, out = idx % 192;
        int grp = out >> 6, f = out & 63;
        const float* W = (grp == 0) ? W_r : (grp == 1) ? W_z : W_h;
        float v = W[f * 192 + k];
        if (grp == 2 && k >= 128) v = 0.f;
        g_WTh[k][out] = __float2half_rn(v);
    }
    if (idx < 64 * 64) {
        int k = idx / 64, f = idx % 64;
        g_Wh2Th[k][f] = __float2half_rn(W_h[f * 192 + 128 + k]);
    }
}

// ---------------------------------------------------------------------------
// s projection (tiled GEMM) -> fp16 S, k-major rows. grid (125, 8), block 256.
// ---------------------------------------------------------------------------
__global__ void __launch_bounds__(256) k_compute_s2(
    const float* __restrict__ Xext, int use_ext,
    const float* __restrict__ W_in, const float* __restrict__ W_out) {
    const float* X = use_ext ? Xext : &g_state[0][0][0][0];
    int rb = blockIdx.x, cb = blockIdx.y;
    __shared__ float x_sm[64][64];
    __shared__ float wT[64][64];
    int t = threadIdx.x;

#pragma unroll
    for (int i = 0; i < 4; i++) {
        int idx = i * 256 + t;
        int r = idx >> 4, c4 = idx & 15;
        int gr = rb * 64 + r;
        *(float4*)&x_sm[r][c4 * 4] = *(const float4*)&X[(size_t)gr * 64 + c4 * 4];
    }
    const float* Wsrc = (cb < 4) ? (W_in + (size_t)cb * 64 * 64)
                                 : (W_out + (size_t)(cb - 4) * 64 * 64);
#pragma unroll
    for (int i = 0; i < 4; i++) {
        int idx = i * 256 + t;
        int cl = idx >> 4, k4 = idx & 15;
        float4 v = *(const float4*)&Wsrc[cl * 64 + k4 * 4];
        wT[k4 * 4 + 0][cl] = v.x;
        wT[k4 * 4 + 1][cl] = v.y;
        wT[k4 * 4 + 2][cl] = v.z;
        wT[k4 * 4 + 3][cl] = v.w;
    }
    __syncthreads();

    int ty = t >> 5, tx = t & 31;
    float acc[8][2];
#pragma unroll
    for (int i = 0; i < 8; i++) { acc[i][0] = 0.f; acc[i][1] = 0.f; }

#pragma unroll
    for (int k4 = 0; k4 < 16; k4++) {
        float4 xv[8];
#pragma unroll
        for (int i = 0; i < 8; i++) xv[i] = *(float4*)&x_sm[ty * 8 + i][k4 * 4];
#pragma unroll
        for (int q = 0; q < 4; q++) {
            float2 wv = *(float2*)&wT[k4 * 4 + q][tx * 2];
#pragma unroll
            for (int i = 0; i < 8; i++) {
                float xs = (q == 0) ? xv[i].x : (q == 1) ? xv[i].y
                         : (q == 2) ? xv[i].z : xv[i].w;
                acc[i][0] += xs * wv.x;
                acc[i][1] += xs * wv.y;
            }
        }
    }

    int cbase = cb * 64 + tx * 2;
    int half = cbase >> 8, e = (cbase >> 6) & 3, f = cbase & 63;
#pragma unroll
    for (int i = 0; i < 8; i++) {
        int gr = rb * 64 + ty * 8 + i;
        int b = gr / 1000, n = gr % 1000;
        __half2 hv = __floats2half2_rn(acc[i][0], acc[i][1]);
        *(__half2*)&g_sh[half][b][e * 1000 + n][f] = hv;
    }
}

// ---------------------------------------------------------------------------
// Big adjacency GEMM: M=64 tiles (traffic-optimal), 256 threads / 8 warps
// (warp tile 16m x 32n) for latency hiding. grid (16, 2, 8), 4-stage
// cp.async, chunk-tiled A' reads, 39 KB static smem.
// ---------------------------------------------------------------------------
__global__ void __launch_bounds__(256) k_biggemm_f16(int dummy) {
    __shared__ __half Asm[4][64 * ASTR];   // 4 x 5120 B
    __shared__ __half Bsm[4][32 * BSTR];   // 4 x 4608 B

    int rb = blockIdx.x, half = blockIdx.y, b = blockIdx.z;
    int row0 = rb * 64;
    const __half* Abh = g_Ah + ((size_t)b * 2 + half) * NCHUNK * CHW;
    const __half* Sbh = &g_sh[half][b][0][0];

    int t = threadIdx.x, lane = t & 31, warp = t >> 5;
    int wm = warp & 3, wn = warp >> 2;

    // A cp.async: 64 rows x 4 segs of 16B = 256 ops -> 1 per thread
    const __half* asrc; uint32_t adst;
    {
        int row = t >> 2, seg = t & 3;
        int gr = row0 + row; if (gr > Nc - 1) gr = Nc - 1;
        asrc = Abh + (size_t)gr * 32 + seg * 8;
        adst = (uint32_t)(row * ASTR + seg * 8) * 2u;
    }
    // B cp.async: 32 rows x 8 segs of 16B = 256 ops -> 1 per thread
    const __half* bsrc; uint32_t bdst;
    {
        int row = t >> 3, seg = t & 7;
        bsrc = Sbh + (size_t)row * Dc + seg * 8;
        bdst = (uint32_t)(row * BSTR + seg * 8) * 2u;
    }

    uint32_t a_base[4], b_base[4];
#pragma unroll
    for (int s = 0; s < 4; s++) {
        a_base[s] = (uint32_t)__cvta_generic_to_shared(&Asm[s][0]);
        b_base[s] = (uint32_t)__cvta_generic_to_shared(&Bsm[s][0]);
    }

    uint32_t a_off[2];
#pragma unroll
    for (int kk = 0; kk < 2; kk++) {
        int row = wm * 16 + ((lane >> 3) & 1) * 8 + (lane & 7);
        int col = kk * 16 + (lane >> 4) * 8;
        a_off[kk] = (uint32_t)(row * ASTR + col) * 2u;
    }
    uint32_t b_off[2][2];   // [g][kk]
#pragma unroll
    for (int g = 0; g < 2; g++)
#pragma unroll
        for (int kk = 0; kk < 2; kk++) {
            int krow = kk * 16 + (lane & 15);
            int ncol = wn * 32 + g * 16 + (lane >> 4) * 8;
            b_off[g][kk] = (uint32_t)(krow * BSTR + ncol) * 2u;
        }

    float acc[4][4];
#pragma unroll
    for (int nt = 0; nt < 4; nt++)
#pragma unroll
        for (int c = 0; c < 4; c++) acc[nt][c] = 0.f;

#pragma unroll
    for (int ch = 0; ch < 3; ch++) {
        cp_async16(a_base[ch] + adst, asrc + (size_t)ch * CHW);
        cp_async16(b_base[ch] + bdst, bsrc + (size_t)ch * KCH * Dc);
        cp_commit();
    }

    for (int i = 0; i < NCHUNK; i++) {
        asm volatile("cp.async.wait_group 2;\n");
        __syncthreads();

        if (i + 3 < NCHUNK) {
            int s = (i + 3) & 3;
            cp_async16(a_base[s] + adst, asrc + (size_t)(i + 3) * CHW);
            cp_async16(b_base[s] + bdst, bsrc + (size_t)(i + 3) * KCH * Dc);
        }
        cp_commit();

        uint32_t ab = a_base[i & 3], bb = b_base[i & 3];
        uint32_t aF[2][4];
        uint32_t bF[2][2][4];
#pragma unroll
        for (int kk = 0; kk < 2; kk++) ldm4(aF[kk], ab + a_off[kk]);
#pragma unroll
        for (int kk = 0; kk < 2; kk++)
#pragma unroll
            for (int g = 0; g < 2; g++) ldm4t(bF[kk][g], bb + b_off[g][kk]);

#pragma unroll
        for (int kk = 0; kk < 2; kk++)
#pragma unroll
            for (int nt = 0; nt < 4; nt++) {
                int g = nt >> 1, sel = nt & 1;
                mma_f16(acc[nt], aF[kk],
                        bF[kk][g][sel * 2], bF[kk][g][sel * 2 + 1]);
            }
    }

    __half (*C)[Dc] = g_ah2[half][b];
    int r_a = row0 + wm * 16 + (lane >> 2);
    int r_b = r_a + 8;
#pragma unroll
    for (int nt = 0; nt < 4; nt++) {
        int col = wn * 32 + nt * 8 + (lane & 3) * 2;
        if (r_a < Nc) *(__half2*)&C[r_a][col] = __floats2half2_rn(acc[nt][0], acc[nt][1]);
        if (r_b < Nc) *(__half2*)&C[r_b][col] = __floats2half2_rn(acc[nt][2], acc[nt][3]);
    }
}

// ---------------------------------------------------------------------------
// Fused tensor-core GRU (unchanged from R14 winner).
// ---------------------------------------------------------------------------
__global__ void __launch_bounds__(128) k_gru(const float* __restrict__ ext_state,
                                             int use_ext, int out_idx) {
    extern __shared__ char gsm[];
    __half* Xh  = (__half*)gsm;                    // [64][200]
    __half* Wsm = (__half*)(gsm + XH_B);           // [192][72]
    __half* RSs = (__half*)(gsm + XH_B + W_B);     // [64][72]
    float*  STs = (float*)(gsm + XH_B + W_B + RS_B); // [64][68]

    int rb = blockIdx.x;
    int row0 = rb * 64;
    int t = threadIdx.x, lane = t & 31, warp = t >> 5;

    uint32_t xh_u  = (uint32_t)__cvta_generic_to_shared(Xh);
    uint32_t wsm_u = (uint32_t)__cvta_generic_to_shared(Wsm);
    uint32_t rs_u  = (uint32_t)__cvta_generic_to_shared(RSs);

#pragma unroll
    for (int j = 0; j < 8; j++) {
        int flat = j * 128 + t;
        int row = flat >> 4, seg = flat & 15;
        int gr = row0 + row;
        int b = gr / 1000, n = gr % 1000;
        const __half* p = (seg < 8) ? &g_ah2[0][b][n][seg * 8]
                                    : &g_ah2[1][b][n][(seg - 8) * 8];
        cp_async16(xh_u + (uint32_t)(row * XSTR + seg * 8) * 2u, p);
    }
#pragma unroll
    for (int j = 0; j < 12; j++) {
        int flat = j * 128 + t;
        int k = flat >> 3, seg = flat & 7;
        cp_async16(wsm_u + (uint32_t)(k * WSTR + seg * 8) * 2u, &g_WTh[k][seg * 8]);
    }
    cp_commit();
#pragma unroll
    for (int j = 0; j < 8; j++) {
        int flat = j * 128 + t;
        int row = flat >> 4, c4 = flat & 15;
        int gr = row0 + row;
        int b = gr / 1000, n = gr % 1000;
        const float* sp = use_ext ? (ext_state + (size_t)gr * 64)
                                  : &g_state[0][b][n][0];
        float4 v = *(const float4*)&sp[c4 * 4];
        *(float4*)&STs[row * SSTR + c4 * 4] = v;
        __half2 h0 = __floats2half2_rn(v.x, v.y);
        __half2 h1 = __floats2half2_rn(v.z, v.w);
        *(uint2*)&Xh[row * XSTR + 128 + c4 * 4] = make_uint2(*(uint32_t*)&h0, *(uint32_t*)&h1);
    }

    int a_row = warp * 16 + ((lane >> 3) & 1) * 8 + (lane & 7);
    int acol8 = (lane >> 4) * 8;
    uint32_t base_a  = xh_u + (uint32_t)(a_row * XSTR + acol8) * 2u;
    uint32_t base_rs = rs_u + (uint32_t)(a_row * RSTR + acol8) * 2u;
    int b_k = lane & 15, bcol = (lane >> 4) * 8;

    float acc[3][8][4];
#pragma unroll
    for (int cb = 0; cb < 3; cb++)
#pragma unroll
        for (int nt = 0; nt < 8; nt++)
#pragma unroll
            for (int c = 0; c < 4; c++) acc[cb][nt][c] = 0.f;

    for (int cb = 0; cb < 3; cb++) {
        asm volatile("cp.async.wait_group 0;\n");
        __syncthreads();

#pragma unroll
        for (int kc = 0; kc < 6; kc++) {
#pragma unroll
            for (int kk = 0; kk < 2; kk++) {
                int kb = kc * 32 + kk * 16;
                uint32_t aF[4];
                ldm4(aF, base_a + (uint32_t)kb * 2u);
                uint32_t bF[4][4];
#pragma unroll
                for (int g = 0; g < 4; g++)
                    ldm4t(bF[g], wsm_u + (uint32_t)((kb + b_k) * WSTR + g * 16 + bcol) * 2u);
#pragma unroll
                for (int nt = 0; nt < 8; nt++) {
                    int g = nt >> 1, sel = nt & 1;
                    mma_f16(acc[cb][nt], aF, bF[g][sel * 2], bF[g][sel * 2 + 1]);
                }
            }
        }
        __syncthreads();

        if (cb < 2) {
#pragma unroll
            for (int j = 0; j < 12; j++) {
                int flat = j * 128 + t;
                int k = flat >> 3, seg = flat & 7;
                cp_async16(wsm_u + (uint32_t)(k * WSTR + seg * 8) * 2u,
                           &g_WTh[k][(cb + 1) * 64 + seg * 8]);
            }
        } else {
#pragma unroll
            for (int j = 0; j < 4; j++) {
                int flat = j * 128 + t;
                int k = flat >> 3, seg = flat & 7;
                cp_async16(wsm_u + (uint32_t)(k * WSTR + seg * 8) * 2u,
                           &g_Wh2Th[k][seg * 8]);
            }
        }
        cp_commit();
    }

    int lr_a = warp * 16 + (lane >> 2);
    int lr_b = lr_a + 8;
#pragma unroll
    for (int nt = 0; nt < 8; nt++) {
        int c = nt * 8 + (lane & 3) * 2;
        float2 sa = *(float2*)&STs[lr_a * SSTR + c];
        float2 sb = *(float2*)&STs[lr_b * SSTR + c];
        float ra0 = sa.x / (1.f + expf(-acc[0][nt][0]));
        float ra1 = sa.y / (1.f + expf(-acc[0][nt][1]));
        float rb0 = sb.x / (1.f + expf(-acc[0][nt][2]));
        float rb1 = sb.y / (1.f + expf(-acc[0][nt][3]));
        *(__half2*)&RSs[lr_a * RSTR + c] = __floats2half2_rn(ra0, ra1);
        *(__half2*)&RSs[lr_b * RSTR + c] = __floats2half2_rn(rb0, rb1);
    }
    asm volatile("cp.async.wait_group 0;\n");
    __syncthreads();

#pragma unroll
    for (int nt = 0; nt < 8; nt++)
#pragma unroll
        for (int c = 0; c < 4; c++) acc[0][nt][c] = 0.f;

#pragma unroll
    for (int kc = 0; kc < 2; kc++) {
#pragma unroll
        for (int kk = 0; kk < 2; kk++) {
            int kb = kc * 32 + kk * 16;
            uint32_t aF[4];
            ldm4(aF, base_rs + (uint32_t)kb * 2u);
            uint32_t bF[4][4];
#pragma unroll
            for (int g = 0; g < 4; g++)
                ldm4t(bF[g], wsm_u + (uint32_t)((kb + b_k) * WSTR + g * 16 + bcol) * 2u);
#pragma unroll
            for (int nt = 0; nt < 8; nt++) {
                int g = nt >> 1, sel = nt & 1;
                mma_f16(acc[0][nt], aF, bF[g][sel * 2], bF[g][sel * 2 + 1]);
            }
        }
    }

#pragma unroll
    for (int nt = 0; nt < 8; nt++) {
        int c = nt * 8 + (lane & 3) * 2;
        float2 sa = *(float2*)&STs[lr_a * SSTR + c];
        float2 sb = *(float2*)&STs[lr_b * SSTR + c];
        float za0 = 1.f / (1.f + expf(-acc[1][nt][0]));
        float za1 = 1.f / (1.f + expf(-acc[1][nt][1]));
        float zb0 = 1.f / (1.f + expf(-acc[1][nt][2]));
        float zb1 = 1.f / (1.f + expf(-acc[1][nt][3]));
        float ha0 = tanhf(acc[2][nt][0] + acc[0][nt][0]);
        float ha1 = tanhf(acc[2][nt][1] + acc[0][nt][1]);
        float hb0 = tanhf(acc[2][nt][2] + acc[0][nt][2]);
        float hb1 = tanhf(acc[2][nt][3] + acc[0][nt][3]);
        int gra = row0 + lr_a, grb = row0 + lr_b;
        int ba = gra / 1000, na = gra % 1000;
        int bb2 = grb / 1000, nb = grb % 1000;
        *(float2*)&g_state[out_idx][ba][na][c] =
            make_float2((1.f - za0) * sa.x + za0 * ha0,
                        (1.f - za1) * sa.y + za1 * ha1);
        *(float2*)&g_state[out_idx][bb2][nb][c] =
            make_float2((1.f - zb0) * sb.x + zb0 * hb0,
                        (1.f - zb1) * sb.y + zb1 * hb1);
    }
}

// ---------------------------------------------------------------------------
// out[b,n] = sum_f tanh( sum_{j<96} [s2|annot][j] * Wo1[f,j] ) * Wo2[f]
// ---------------------------------------------------------------------------
__global__ void k_final(const float* __restrict__ annotation,
                        const float* __restrict__ Wo1,
                        const float* __restrict__ Wo2,
                        float* __restrict__ out) {
    __shared__ float join[4][96];
    __shared__ float terms[4][64];
    int t = threadIdx.x;
    int base = blockIdx.x * 4;

    for (int idx = t; idx < 4 * 96; idx += 256) {
        int lr = idx / 96, j = idx % 96;
        int bn = base + lr;
        int b = bn / Nc, n = bn % Nc;
        join[lr][j] = (j < Dc) ? g_state[1][b][n][j]
                               : annotation[(size_t)bn * ADc + (j - Dc)];
    }
    __syncthreads();

    int f = t & 63, q = t >> 6;
    const float4* w = (const float4*)(Wo1 + (size_t)f * 96);
    float acc = 0.f;
#pragma unroll
    for (int j4 = 0; j4 < 24; j4++) {
        float4 wv = w[j4];
        float4 jv = *(float4*)&join[q][j4 * 4];
        acc += wv.x * jv.x + wv.y * jv.y + wv.z * jv.z + wv.w * jv.w;
    }
    terms[q][f] = tanhf(acc) * Wo2[f];
    __syncthreads();

    if (f == 0) {
        float s = 0.f;
#pragma unroll
        for (int i = 0; i < Dc; i++) s += terms[q][i];
        out[base + q] = s;
    }
}

// ---------------------------------------------------------------------------
extern "C" void kernel_launch(void* const* d_in, const int* in_sizes, int n_in,
                              void* d_out, int out_size) {
    const float* prop_state = (const float*)d_in[0];
    const float* annotation = (const float*)d_in[1];
    const float* A          = (const float*)d_in[2];
    const float* W_in       = (const float*)d_in[3];
    const float* W_out      = (const float*)d_in[4];
    const float* W_r        = (const float*)d_in[5];
    const float* W_z        = (const float*)d_in[6];
    const float* W_h        = (const float*)d_in[7];
    const float* Wo1        = (const float*)d_in[8];
    const float* Wo2        = (const float*)d_in[9];
    float* out = (float*)d_out;

    static int smem_set = 0;
    if (!smem_set) {
        cudaFuncSetAttribute(k_gru,
                             cudaFuncAttributeMaxDynamicSharedMemorySize, GRU_SMEM);
        smem_set = 1;
    }

    dim3 s_grid(125, 8);
    dim3 gemm_grid(16, 2, Bc);

    k_convA<<<Bc * Nc * ACOLS / 4 / 256, 256>>>(A);
    k_prepW<<<144, 256>>>(W_r, W_z, W_h);

    // ---- propagate step 1 (state = prop_state) ----
    k_compute_s2<<<s_grid, 256>>>(prop_state, 1, W_in, W_out);
    k_biggemm_f16<<<gemm_grid, 256>>>(0);
    k_gru<<<125, 128, GRU_SMEM>>>(prop_state, 1, 0);

    // ---- propagate step 2 (state = g_state[0]) ----
    k_compute_s2<<<s_grid, 256>>>(nullptr, 0, W_in, W_out);
    k_biggemm_f16<<<gemm_grid, 256>>>(0);
    k_gru<<<125, 128, GRU_SMEM>>>(nullptr, 0, 1);

    // ---- output head ----
    k_final<<<Bc * Nc / 4, 256>>>(annotation, Wo1, Wo2, out);
}